// round 3
// baseline (speedup 1.0000x reference)
#include <cuda_runtime.h>
#include <cuda_fp8.h>
#include <cstdint>

#define DIM 2048
#define NB  (DIM / 32)   // 64 scale blocks per row

// ---------------- scratch (device globals: no allocation allowed) ----------------
__device__ uint8_t g_xq[DIM * DIM];   // x quantized e4m3
__device__ uint8_t g_wq[DIM * DIM];   // w quantized e4m3
__device__ float   g_sx[DIM * NB];    // x block scales
__device__ float   g_sw[DIM * NB];    // w block scales

// ---------------- fused quantizer: 8 threads per 32-elem block ----------------
// One thread = one float4 (4 elems). Butterfly max over the 8-lane group.
__global__ void __launch_bounds__(256) quant2_kernel(
        const float* __restrict__ x, const float* __restrict__ w,
        uint8_t* __restrict__ xq, uint8_t* __restrict__ wq,
        float* __restrict__ sx, float* __restrict__ sw) {
    const int gtid = blockIdx.x * blockDim.x + threadIdx.x;
    const int half = DIM * DIM / 4;                 // float4 count per tensor
    const bool isW = gtid >= half;
    const int t = isW ? gtid - half : gtid;
    const float4 v = (isW ? reinterpret_cast<const float4*>(w)
                          : reinterpret_cast<const float4*>(x))[t];
    float m = fmaxf(fmaxf(fabsf(v.x), fabsf(v.y)), fmaxf(fabsf(v.z), fabsf(v.w)));
    m = fmaxf(m, __shfl_xor_sync(0xFFFFFFFFu, m, 1));
    m = fmaxf(m, __shfl_xor_sync(0xFFFFFFFFu, m, 2));
    m = fmaxf(m, __shfl_xor_sync(0xFFFFFFFFu, m, 4));
    const float s = fmaxf(__fdiv_rn(m, 448.0f), 1e-30f);

    uint32_t pk = 0;
    const float e[4] = {v.x, v.y, v.z, v.w};
#pragma unroll
    for (int j = 0; j < 4; j++) {
        float qv = __fdiv_rn(e[j], s);              // RN div, matches jnp
        pk |= ((uint32_t)(uint8_t)__nv_cvt_float_to_fp8(qv, __NV_SATFINITE, __NV_E4M3)) << (8 * j);
    }
    reinterpret_cast<uint32_t*>(isW ? wq : xq)[t] = pk;
    if ((t & 7) == 0) (isW ? sw : sx)[t >> 3] = s;
}

// ---------------- GEMM: CTA tile 128x256, 8 warps of 64x64, fp8 mma + f32x2 scaling ----
// Stage: A 16KB | B 32KB | SX 2KB | SW 4KB = 55296 B; two stages = 110592 B.
static constexpr int STG      = 55296;
static constexpr int OFF_B    = 16384;
static constexpr int OFF_SX   = 49152;
static constexpr int OFF_SW   = 51200;
static constexpr int SMEM_TOT = 2 * STG;

#define SWZ_OFF(r, c) (((r) * 128) + ((((c) ^ ((r) & 7)) & 7) << 4))

__device__ __forceinline__ void cp16(uint32_t saddr, const void* gptr) {
    asm volatile("cp.async.cg.shared.global [%0], [%1], 16;"
                 :: "r"(saddr), "l"(__cvta_generic_to_global(gptr)));
}
__device__ __forceinline__ void cp16ca(uint32_t saddr, const void* gptr) {
    asm volatile("cp.async.ca.shared.global [%0], [%1], 16;"
                 :: "r"(saddr), "l"(__cvta_generic_to_global(gptr)));
}

__device__ __forceinline__ unsigned long long pk2(float lo, float hi) {
    unsigned long long r;
    asm("mov.b64 %0, {%1, %2};" : "=l"(r) : "f"(lo), "f"(hi));
    return r;
}
__device__ __forceinline__ unsigned long long mul2(unsigned long long a, unsigned long long b) {
    unsigned long long r;
    asm("mul.rn.f32x2 %0, %1, %2;" : "=l"(r) : "l"(a), "l"(b));
    return r;
}
__device__ __forceinline__ unsigned long long fma2(unsigned long long a, unsigned long long b,
                                                   unsigned long long c) {
    unsigned long long r;
    asm("fma.rn.f32x2 %0, %1, %2, %3;" : "=l"(r) : "l"(a), "l"(b), "l"(c));
    return r;
}

__global__ void __launch_bounds__(256, 1)
gemm_kernel(const float* __restrict__ bias, float* __restrict__ out) {
    extern __shared__ char smem[];
    const uint32_t sbase = (uint32_t)__cvta_generic_to_shared(smem);
    const int tid  = threadIdx.x;
    const int lane = tid & 31, warp = tid >> 5;
    const int m0 = blockIdx.y * 128, n0 = blockIdx.x * 256;
    const int wm0 = (warp >> 2) * 64, wn0 = (warp & 3) * 64;

    // acc[mt][nt][0] = rows r0 (cols cj,cj+1), [1] = rows r0+8
    unsigned long long acc[4][8][2];
#pragma unroll
    for (int i = 0; i < 4; i++)
#pragma unroll
        for (int j = 0; j < 8; j++) { acc[i][j][0] = 0ull; acc[i][j][1] = 0ull; }

    auto load_stage = [&](int kc, int st) {
        const uint32_t sb = sbase + st * STG;
#pragma unroll
        for (int i = 0; i < 4; i++) {   // A: 1024 x 16B chunks
            const int idx = tid * 4 + i;
            const int r = idx >> 3, c = idx & 7;
            cp16(sb + SWZ_OFF(r, c), g_xq + (size_t)(m0 + r) * DIM + kc * 128 + c * 16);
        }
#pragma unroll
        for (int i = 0; i < 8; i++) {   // B: 2048 x 16B chunks
            const int idx = tid * 8 + i;
            const int r = idx >> 3, c = idx & 7;
            cp16(sb + OFF_B + SWZ_OFF(r, c), g_wq + (size_t)(n0 + r) * DIM + kc * 128 + c * 16);
        }
        if (tid < 128)
            cp16ca(sb + OFF_SX + tid * 16, g_sx + (size_t)(m0 + tid) * NB + kc * 4);
        cp16ca(sb + OFF_SW + tid * 16, g_sw + (size_t)(n0 + tid) * NB + kc * 4);
    };

    load_stage(0, 0);
    asm volatile("cp.async.commit_group;" ::: "memory");

#pragma unroll 1
    for (int kc = 0; kc < 16; kc++) {
        const int st = kc & 1;
        if (kc + 1 < 16) load_stage(kc + 1, st ^ 1);
        asm volatile("cp.async.commit_group;" ::: "memory");
        asm volatile("cp.async.wait_group 1;" ::: "memory");
        __syncthreads();

        const uint32_t sb = sbase + st * STG;
        const char* ss = smem + st * STG;

#pragma unroll
        for (int b = 0; b < 4; b++) {   // 4 scale-blocks (K=32) per 128B chunk
            // A fragments: 4 m-tiles of 16 rows
            uint32_t af[4][4];
#pragma unroll
            for (int mt = 0; mt < 4; mt++) {
                const int r = wm0 + mt * 16 + (lane & 15);
                const int c = 2 * b + (lane >> 4);
                asm volatile("ldmatrix.sync.aligned.m8n8.x4.shared.b16 {%0,%1,%2,%3}, [%4];"
                             : "=r"(af[mt][0]), "=r"(af[mt][1]), "=r"(af[mt][2]), "=r"(af[mt][3])
                             : "r"(sb + SWZ_OFF(r, c)));
            }
            // packed A-row scales for this block
            unsigned long long sxaa[4], sxbb[4];
#pragma unroll
            for (int mt = 0; mt < 4; mt++) {
                const int r = wm0 + mt * 16 + (lane >> 2);
                float a = *reinterpret_cast<const float*>(ss + OFF_SX + r * 16 + b * 4);
                float bb = *reinterpret_cast<const float*>(ss + OFF_SX + (r + 8) * 16 + b * 4);
                sxaa[mt] = pk2(a, a);
                sxbb[mt] = pk2(bb, bb);
            }
#pragma unroll
            for (int nt = 0; nt < 8; nt++) {
                uint32_t bf0, bf1;
                {
                    const int r = wn0 + nt * 8 + (lane & 7);
                    const int c = 2 * b + ((lane >> 3) & 1);
                    asm volatile("ldmatrix.sync.aligned.m8n8.x2.shared.b16 {%0,%1}, [%2];"
                                 : "=r"(bf0), "=r"(bf1)
                                 : "r"(sb + OFF_B + SWZ_OFF(r, c)));
                }
                const int cj = wn0 + nt * 8 + ((lane & 3) << 1);
                const unsigned long long sw01 =
                    pk2(*reinterpret_cast<const float*>(ss + OFF_SW + cj * 16 + b * 4),
                        *reinterpret_cast<const float*>(ss + OFF_SW + (cj + 1) * 16 + b * 4));
#pragma unroll
                for (int mt = 0; mt < 4; mt++) {
                    float d0, d1, d2, d3;
                    asm volatile(
                        "mma.sync.aligned.m16n8k32.row.col.f32.e4m3.e4m3.f32 "
                        "{%0,%1,%2,%3}, {%4,%5,%6,%7}, {%8,%9}, {%10,%11,%12,%13};"
                        : "=f"(d0), "=f"(d1), "=f"(d2), "=f"(d3)
                        : "r"(af[mt][0]), "r"(af[mt][1]), "r"(af[mt][2]), "r"(af[mt][3]),
                          "r"(bf0), "r"(bf1),
                          "f"(0.f), "f"(0.f), "f"(0.f), "f"(0.f));
                    acc[mt][nt][0] = fma2(mul2(sxaa[mt], sw01), pk2(d0, d1), acc[mt][nt][0]);
                    acc[mt][nt][1] = fma2(mul2(sxbb[mt], sw01), pk2(d2, d3), acc[mt][nt][1]);
                }
            }
        }
        __syncthreads();
    }

    // ---- epilogue: add bias, store fp32 ----
#pragma unroll
    for (int mt = 0; mt < 4; mt++) {
        const int r0 = m0 + wm0 + mt * 16 + (lane >> 2);
#pragma unroll
        for (int nt = 0; nt < 8; nt++) {
            const int cj = n0 + wn0 + nt * 8 + ((lane & 3) << 1);
            const float2 bz = *reinterpret_cast<const float2*>(bias + cj);
            const unsigned long long a0 = acc[mt][nt][0], a1 = acc[mt][nt][1];
            float2 o0 = make_float2(__uint_as_float((uint32_t)a0) + bz.x,
                                    __uint_as_float((uint32_t)(a0 >> 32)) + bz.y);
            float2 o1 = make_float2(__uint_as_float((uint32_t)a1) + bz.x,
                                    __uint_as_float((uint32_t)(a1 >> 32)) + bz.y);
            *reinterpret_cast<float2*>(out + (size_t)r0 * DIM + cj) = o0;
            *reinterpret_cast<float2*>(out + (size_t)(r0 + 8) * DIM + cj) = o1;
        }
    }
}

// ---------------- launch ----------------
extern "C" void kernel_launch(void* const* d_in, const int* in_sizes, int n_in,
                              void* d_out, int out_size) {
    const float* x    = (const float*)d_in[0];
    const float* w    = (const float*)d_in[1];
    const float* bias = (const float*)d_in[2];
    float* out = (float*)d_out;

    void *xq, *wq, *sx, *sw;
    cudaGetSymbolAddress(&xq, g_xq);
    cudaGetSymbolAddress(&wq, g_wq);
    cudaGetSymbolAddress(&sx, g_sx);
    cudaGetSymbolAddress(&sw, g_sw);

    cudaFuncSetAttribute(gemm_kernel, cudaFuncAttributeMaxDynamicSharedMemorySize, SMEM_TOT);

    const int nthreads = 2 * DIM * DIM / 4;         // 8 threads per 32-elem block, 2 tensors
    quant2_kernel<<<nthreads / 256, 256>>>(x, w, (uint8_t*)xq, (uint8_t*)wq,
                                           (float*)sx, (float*)sw);
    gemm_kernel<<<dim3(8, 16), 256, SMEM_TOT>>>(bias, out);
}